// round 10
// baseline (speedup 1.0000x reference)
#include <cuda_runtime.h>
#include <cuda_bf16.h>
#include <cstdint>
#include <math.h>

#define BATCH 4
#define NPTS  8192
#define DIM   128
#define DOUT  256
#define NH    4
#define HD    64
#define KNBR  16
#define ROWS  (BATCH*NPTS)          // 32768
#define NROWS (BATCH*NPTS*KNBR)     // 524288

// ---------------- scratch (device globals; no runtime alloc) ----------------
__device__ float4 g_xyzw[ROWS];
__device__ int    g_knn[NROWS];
__device__ __nv_bfloat16 g_feat_h[ROWS*DIM];
__device__ __nv_bfloat16 g_feat_l[ROWS*DIM];
__device__ __nv_bfloat16 g_lnf_h[ROWS*DIM];
__device__ __nv_bfloat16 g_lnf_l[ROWS*DIM];
__device__ float  g_qkv[(size_t)ROWS*768];
__device__ float  g_lnq[ROWS*DOUT];
__device__ __nv_bfloat16 g_posb[(size_t)NROWS*HD];
__device__ __nv_bfloat16 g_mid_h[ROWS*DOUT];
__device__ __nv_bfloat16 g_mid_l[ROWS*DOUT];
__device__ __nv_bfloat16 g_fc1_h[ROWS*DOUT];
__device__ __nv_bfloat16 g_fc1_l[ROWS*DOUT];
__device__ float  g_fc2[ROWS*DOUT];
__device__ __nv_bfloat16 g_wqkvT_h[768*DIM];
__device__ __nv_bfloat16 g_wqkvT_l[768*DIM];
__device__ __nv_bfloat16 g_wp2T_h[HD*HD];
__device__ __nv_bfloat16 g_wf1T_h[DOUT*DOUT];
__device__ __nv_bfloat16 g_wf1T_l[DOUT*DOUT];
__device__ __nv_bfloat16 g_wf2T_h[DOUT*DOUT];
__device__ __nv_bfloat16 g_wf2T_l[DOUT*DOUT];
__device__ float g_bqkv[768];

// ---------------- small helpers ----------------
__device__ __forceinline__ unsigned pk2(float a, float b) {
    __nv_bfloat162 t = __floats2bfloat162_rn(a, b);
    return *(unsigned*)&t;
}
__device__ __forceinline__ float rndbf(float x) {
    return __bfloat162float(__float2bfloat16_rn(x));
}
__device__ __forceinline__ uint32_t smem_u32(const void* p) {
    uint32_t a;
    asm("{ .reg .u64 t; cvta.to.shared.u64 t, %1; cvt.u32.u64 %0, t; }" : "=r"(a) : "l"(p));
    return a;
}
__device__ __forceinline__ uint32_t swz(uint32_t x) { return x ^ ((x >> 3) & 0x70); }

__device__ __forceinline__ void ldsm4(uint32_t* r, uint32_t addr) {
    asm volatile("ldmatrix.sync.aligned.m8n8.x4.shared.b16 {%0,%1,%2,%3}, [%4];"
        : "=r"(r[0]), "=r"(r[1]), "=r"(r[2]), "=r"(r[3]) : "r"(addr));
}
__device__ __forceinline__ void mma16816(float* c, const uint32_t* a, uint32_t b0, uint32_t b1) {
    asm volatile("mma.sync.aligned.m16n8k16.row.col.f32.bf16.bf16.f32 "
        "{%0,%1,%2,%3}, {%4,%5,%6,%7}, {%8,%9}, {%0,%1,%2,%3};"
        : "+f"(c[0]), "+f"(c[1]), "+f"(c[2]), "+f"(c[3])
        : "r"(a[0]), "r"(a[1]), "r"(a[2]), "r"(a[3]), "r"(b0), "r"(b1));
}
#define CP16(dst, src) asm volatile("cp.async.cg.shared.global [%0], [%1], 16;" :: "r"(dst), "l"(src))
#define CP_COMMIT()    asm volatile("cp.async.commit_group;" ::: "memory")
#define CP_WAIT1()     asm volatile("cp.async.wait_group 1;" ::: "memory")

// ---------------- merged prep ----------------
#define PREP_BLOCKS 4284

__device__ __forceinline__ void tileT(const float* __restrict__ W,
                                      __nv_bfloat16* Th, __nv_bfloat16* Tl,
                                      int Kd, int Nd, int k0, int n0,
                                      int tid, float (*ts)[65]) {
    #pragma unroll
    for (int i = 0; i < 16; ++i) {
        int e = tid + i*256;
        int r = e >> 6, c = e & 63;
        ts[r][c] = W[(size_t)(k0 + r) * Nd + n0 + c];
    }
    __syncthreads();
    #pragma unroll
    for (int i = 0; i < 16; ++i) {
        int e = tid + i*256;
        int kk = e & 63, nn = e >> 6;
        float x = ts[kk][nn];
        size_t o = (size_t)(n0 + nn) * Kd + k0 + kk;
        float hx = rndbf(x);
        Th[o] = __float2bfloat16_rn(x);
        if (Tl) Tl[o] = __float2bfloat16_rn(x - hx);
    }
}

__global__ void __launch_bounds__(256) k_prep(
    const float* __restrict__ xyz, const float* __restrict__ features,
    const float* __restrict__ Wq, const float* __restrict__ Wk, const float* __restrict__ Wv,
    const float* __restrict__ Wp2, const float* __restrict__ Wf1, const float* __restrict__ Wf2,
    const float* __restrict__ g1, const float* __restrict__ b1,
    const float* __restrict__ bq, const float* __restrict__ bk, const float* __restrict__ bv)
{
    __shared__ float ts[64][65];
    int bid = blockIdx.x, tid = threadIdx.x;
    if (bid < 128) {
        int i = bid * 256 + tid;
        float x = xyz[i*3+0], y = xyz[i*3+1], z = xyz[i*3+2];
        g_xyzw[i] = make_float4(x, y, z, x*x + y*y + z*z);
    } else if (bid < 4224) {
        int row = (bid - 128) * 8 + (tid >> 5);
        int lane = tid & 31;
        float4 v = ((const float4*)(features + (size_t)row * DIM))[lane];
        int idx = row*32 + lane;
        {
            float hx = rndbf(v.x), hy = rndbf(v.y), hz = rndbf(v.z), hw = rndbf(v.w);
            ((uint2*)g_feat_h)[idx] = make_uint2(pk2(v.x, v.y), pk2(v.z, v.w));
            ((uint2*)g_feat_l)[idx] = make_uint2(pk2(v.x-hx, v.y-hy), pk2(v.z-hz, v.w-hw));
        }
        float s = v.x + v.y + v.z + v.w;
        #pragma unroll
        for (int o = 16; o; o >>= 1) s += __shfl_xor_sync(~0u, s, o);
        float mu = s * (1.f/128.f);
        float dx = v.x-mu, dy = v.y-mu, dz = v.z-mu, dw = v.w-mu;
        float s2 = dx*dx + dy*dy + dz*dz + dw*dw;
        #pragma unroll
        for (int o = 16; o; o >>= 1) s2 += __shfl_xor_sync(~0u, s2, o);
        float rs = rsqrtf(s2 * (1.f/128.f) + 1e-5f);
        float4 gg = ((const float4*)g1)[lane];
        float4 bb = ((const float4*)b1)[lane];
        float rx = dx*rs*gg.x + bb.x, ry = dy*rs*gg.y + bb.y;
        float rz = dz*rs*gg.z + bb.z, rw = dw*rs*gg.w + bb.w;
        float hx = rndbf(rx), hy = rndbf(ry), hz = rndbf(rz), hw = rndbf(rw);
        ((uint2*)g_lnf_h)[idx] = make_uint2(pk2(rx, ry), pk2(rz, rw));
        ((uint2*)g_lnf_l)[idx] = make_uint2(pk2(rx-hx, ry-hy), pk2(rz-hz, rw-hw));
    } else if (bid < 4248) {
        int b2 = bid - 4224;
        int m = b2 >> 3, tt = b2 & 7;
        const float* W = m == 0 ? Wq : (m == 1 ? Wk : Wv);
        tileT(W, g_wqkvT_h + m*256*DIM, g_wqkvT_l + m*256*DIM,
              DIM, DOUT, (tt & 1)*64, (tt >> 1)*64, tid, ts);
    } else if (bid < 4249) {
        tileT(Wp2, g_wp2T_h, nullptr, HD, HD, 0, 0, tid, ts);
    } else if (bid < 4265) {
        int b2 = bid - 4249;
        tileT(Wf1, g_wf1T_h, g_wf1T_l, DOUT, DOUT, (b2 & 3)*64, (b2 >> 2)*64, tid, ts);
    } else if (bid < 4281) {
        int b2 = bid - 4265;
        tileT(Wf2, g_wf2T_h, g_wf2T_l, DOUT, DOUT, (b2 & 3)*64, (b2 >> 2)*64, tid, ts);
    } else {
        int t = (bid - 4281) * 256 + tid;
        if (t < 256)      g_bqkv[t] = bq[t];
        else if (t < 512) g_bqkv[t] = bk[t-256];
        else              g_bqkv[t] = bv[t-512];
    }
}

// ---------------- KNN ----------------
#define KNN_CAP 256
#define SMEM_KNN (32768 + 16*KNN_CAP*8)

__global__ void __launch_bounds__(512) k_knn2() {
    extern __shared__ char sk[];
    float4* tile = (float4*)sk;
    float*  bkey = (float*)(sk + 32768);
    int*    bidx = (int*)(sk + 32768 + 16*KNN_CAP*4);
    int t = threadIdx.x, lane = t & 31, w = t >> 5;
    int b = blockIdx.y;
    int q = blockIdx.x * 16 + w;
    const float INF = 3.402823e38f;

    float4 me = g_xyzw[b*NPTS + q];
    float qx2 = -2.f*me.x, qy2 = -2.f*me.y, qz2 = -2.f*me.z;

    float T = 0.f;
    int base = 0;
    float* mk = bkey + w*KNN_CAP;
    int*   mi = bidx + w*KNN_CAP;

    for (int ti = 0; ti < 4; ++ti) {
        __syncthreads();
        for (int i = t; i < 2048; i += 512)
            tile[i] = g_xyzw[b*NPTS + ti*2048 + i];
        __syncthreads();

        if (ti == 0) {
            float mn = INF;
            #pragma unroll 8
            for (int i = 0; i < 64; ++i) {
                float4 p = tile[i*32 + lane];
                float d = fmaf(qx2,p.x,fmaf(qy2,p.y,fmaf(qz2,p.z,p.w)));
                mn = fminf(mn, d);
            }
            float v = mn;
            #pragma unroll
            for (int k = 2; k <= 32; k <<= 1) {
                #pragma unroll
                for (int j = k >> 1; j > 0; j >>= 1) {
                    float o = __shfl_xor_sync(~0u, v, j);
                    bool up = ((lane & k) == 0);
                    bool lower = ((lane & j) == 0);
                    v = (lower == up) ? fminf(v, o) : fmaxf(v, o);
                }
            }
            T = __shfl_sync(~0u, v, 15);
        }

        #pragma unroll 4
        for (int c = 0; c < 64; ++c) {
            int j = c*32 + lane;
            float4 p = tile[j];
            float d = fmaf(qx2,p.x,fmaf(qy2,p.y,fmaf(qz2,p.z,p.w)));
            bool pass = (d <= T);
            unsigned m = __ballot_sync(~0u, pass);
            if (pass) {
                int pos = base + __popc(m & ((1u << lane) - 1u));
                if (pos < KNN_CAP) { mk[pos] = d; mi[pos] = ti*2048 + j; }
            }
            base += __popc(m);
        }
    }
    if (base > KNN_CAP) base = KNN_CAP;
    __syncwarp();

    size_t ob = ((size_t)b*NPTS + q) * KNBR;
    for (int r = 0; r < KNBR; ++r) {
        float bk = INF; int bi = 0x7fffffff; int bp = -1;
        for (int i = lane; i < base; i += 32) {
            float kk = mk[i];
            int   ii = mi[i];
            if (kk < bk || (kk == bk && ii < bi)) { bk = kk; bi = ii; bp = i; }
        }
        #pragma unroll
        for (int o = 16; o; o >>= 1) {
            float ok = __shfl_xor_sync(~0u, bk, o);
            int   oi = __shfl_xor_sync(~0u, bi, o);
            int   op = __shfl_xor_sync(~0u, bp, o);
            if (ok < bk || (ok == bk && oi < bi)) { bk = ok; bi = oi; bp = op; }
        }
        if (lane == 0) {
            g_knn[ob + r] = bi;
            if (bp >= 0) mk[bp] = INF;
        }
        __syncwarp();
    }
}

// ---------------- mma GEMM: CTA 128x64, 4 warps (32x64 warp tile), cp.async 2-stage ----------------
// LDS-balanced: 48KB crossbar traffic per chunk vs 64KB with 8 warps.
#define MG_STGB  24576
#define MG_SMEM  (2*MG_STGB)

__global__ void __launch_bounds__(128, 4) k_mgemm(
    const __nv_bfloat16* __restrict__ Ah, const __nv_bfloat16* __restrict__ Al,
    const __nv_bfloat16* __restrict__ Bh, const __nv_bfloat16* __restrict__ Bl,
    const float* __restrict__ bias,
    float* Cf, __nv_bfloat16* Ch, __nv_bfloat16* Cl,
    int K, int ldc, int relu)
{
    extern __shared__ char sm[];
    uint32_t smb = smem_u32(sm);
    int t = threadIdx.x, lane = t & 31, wm = t >> 5;   // 4 warps, wm = m-block
    int c0 = blockIdx.y * 64;
    int r0 = blockIdx.x * 128;
    int nch = K >> 5;

    float acc[2][8][4];
    #pragma unroll
    for (int i = 0; i < 2; ++i)
        #pragma unroll
        for (int j = 0; j < 8; ++j)
            #pragma unroll
            for (int e = 0; e < 4; ++e) acc[i][j][e] = 0.f;

    int lrow = lane & 15;
    int lcb  = (lane >> 4) * 16;

    auto issue = [&](int c, int stg) {
        int kc = c * 32;
        uint32_t Ab = smb + stg*MG_STGB;
        uint32_t Bb = Ab + 16384;
        #pragma unroll
        for (int i = 0; i < 8; ++i) {
            int e = t + i*128;
            int row = e >> 3, seg = e & 7;
            const __nv_bfloat16* src = (seg < 4 ? Ah : Al) + (size_t)(r0+row)*K + kc + (seg & 3)*8;
            CP16(Ab + swz((uint32_t)row*128 + seg*16), src);
        }
        #pragma unroll
        for (int i = 0; i < 4; ++i) {
            int e = t + i*128;
            int row = e >> 3, seg = e & 7;
            const __nv_bfloat16* src = (seg < 4 ? Bh : Bl) + (size_t)(c0+row)*K + kc + (seg & 3)*8;
            CP16(Bb + swz((uint32_t)row*128 + seg*16), src);
        }
    };

    issue(0, 0); CP_COMMIT();
    issue(1, 1); CP_COMMIT();

    for (int c = 0; c < nch; ++c) {
        CP_WAIT1();
        __syncthreads();
        uint32_t Ab = smb + (c & 1)*MG_STGB;
        uint32_t Bb = Ab + 16384;
        #pragma unroll
        for (int s = 0; s < 2; ++s) {
            int kb = s*32 + lcb;
            uint32_t ah[2][4], al[2][4];
            #pragma unroll
            for (int mb = 0; mb < 2; ++mb) {
                uint32_t ro = (uint32_t)(wm*32 + mb*16 + lrow)*128;
                ldsm4(ah[mb], Ab + swz(ro + kb));
                ldsm4(al[mb], Ab + swz(ro + 64 + kb));
            }
            #pragma unroll
            for (int nb = 0; nb < 4; ++nb) {
                uint32_t bh[4], bl[4];
                uint32_t ro = (uint32_t)(nb*16 + lrow)*128;
                ldsm4(bh, Bb + swz(ro + kb));
                ldsm4(bl, Bb + swz(ro + 64 + kb));
                #pragma unroll
                for (int mb = 0; mb < 2; ++mb) {
                    float* cA = acc[mb][nb*2];
                    float* cB = acc[mb][nb*2+1];
                    mma16816(cA, ah[mb], bh[0], bh[2]);
                    mma16816(cB, ah[mb], bh[1], bh[3]);
                    mma16816(cA, ah[mb], bl[0], bl[2]);
                    mma16816(cB, ah[mb], bl[1], bl[3]);
                    mma16816(cA, al[mb], bh[0], bh[2]);
                    mma16816(cB, al[mb], bh[1], bh[3]);
                }
            }
        }
        __syncthreads();
        if (c + 2 < nch) issue(c + 2, c & 1);
        CP_COMMIT();
    }

    int rbase = r0 + wm*32 + (lane >> 2);
    int cb = c0 + (lane & 3)*2;
    #pragma unroll
    for (int mb = 0; mb < 2; ++mb) {
        #pragma unroll
        for (int nn = 0; nn < 8; ++nn) {
            int col = cb + nn*8;
            float b0 = bias[col], b1 = bias[col+1];
            float v0 = acc[mb][nn][0] + b0, v1 = acc[mb][nn][1] + b1;
            float v2 = acc[mb][nn][2] + b0, v3 = acc[mb][nn][3] + b1;
            if (relu) {
                v0 = fmaxf(v0, 0.f); v1 = fmaxf(v1, 0.f);
                v2 = fmaxf(v2, 0.f); v3 = fmaxf(v3, 0.f);
            }
            size_t ra = (size_t)(rbase + mb*16) * ldc + col;
            size_t rb = (size_t)(rbase + mb*16 + 8) * ldc + col;
            if (Cf) {
                *(float2*)(Cf + ra) = make_float2(v0, v1);
                *(float2*)(Cf + rb) = make_float2(v2, v3);
            }
            if (Ch) {
                float h0 = rndbf(v0), h1 = rndbf(v1), h2 = rndbf(v2), h3 = rndbf(v3);
                *(unsigned*)(Ch + ra) = pk2(v0, v1);
                *(unsigned*)(Cl + ra) = pk2(v0-h0, v1-h1);
                *(unsigned*)(Ch + rb) = pk2(v2, v3);
                *(unsigned*)(Cl + rb) = pk2(v2-h2, v3-h3);
            }
        }
    }
}

// ---------------- fused pos GEMM: smem Wp1, float4 xyzw, bf16 out ----------------
#define PG_A 0
#define PG_B 16384
#define PG_W 24576
#define SMEM_PG (24576 + 1024)

__global__ void __launch_bounds__(256) k_pgemm(
    const float* __restrict__ Wp1, const float* __restrict__ bp1,
    const float* __restrict__ bias)
{
    extern __shared__ char sm[];
    uint32_t smb = smem_u32(sm);
    float* ws = (float*)(sm + PG_W);
    int t = threadIdx.x, lane = t & 31, w = t >> 5;
    int wm = w & 3, wn = w >> 2;
    int r0 = blockIdx.x * 128;

    if (t < 192) ws[t] = Wp1[t];
    else ws[t] = bp1[t - 192];
    #pragma unroll 2
    for (int e = t; e < 512; e += 256) {
        int row = e >> 3, vo = e & 7;
        *(uint4*)(sm + PG_B + swz(row*128 + vo*16)) = *(const uint4*)(g_wp2T_h + row*64 + vo*8);
    }
    __syncthreads();

    {
        int row = t >> 1, ch = t & 1;
        int rr = r0 + row;
        int b = rr >> 17, n = (rr >> 4) & (NPTS - 1);
        int idx = g_knn[rr];
        float4 nbp = g_xyzw[(b << 13) + idx];
        float4 ctp = g_xyzw[(b << 13) + n];
        float rx = nbp.x - ctp.x, ry = nbp.y - ctp.y, rz = nbp.z - ctp.z;
        uint32_t hp[16];
        #pragma unroll
        for (int cc = 0; cc < 32; cc += 2) {
            int c = ch*32 + cc;
            float v0 = fmaf(rx, ws[c],   fmaf(ry, ws[64+c],   fmaf(rz, ws[128+c],   ws[192+c])));
            float v1 = fmaf(rx, ws[c+1], fmaf(ry, ws[64+c+1], fmaf(rz, ws[128+c+1], ws[192+c+1])));
            hp[cc>>1] = pk2(fmaxf(v0, 0.f), fmaxf(v1, 0.f));
        }
        uint32_t rbyte = (uint32_t)row*128 + ch*64;
        #pragma unroll
        for (int i = 0; i < 4; ++i)
            *(uint4*)(sm + PG_A + swz(rbyte + i*16)) = *(uint4*)&hp[i*4];
    }
    __syncthreads();

    float acc[2][4][4];
    #pragma unroll
    for (int i = 0; i < 2; ++i)
        #pragma unroll
        for (int j = 0; j < 4; ++j)
            #pragma unroll
            for (int e = 0; e < 4; ++e) acc[i][j][e] = 0.f;
    int lrow = lane & 15, lcolb = (lane >> 4) * 16;
    #pragma unroll
    for (int s = 0; s < 4; ++s) {
        int kb = s*32 + lcolb;
        uint32_t ah[2][4];
        #pragma unroll
        for (int mb = 0; mb < 2; ++mb)
            ldsm4(ah[mb], smb + PG_A + swz((uint32_t)(wm*32 + mb*16 + lrow)*128 + kb));
        #pragma unroll
        for (int nb = 0; nb < 2; ++nb) {
            uint32_t bh[4];
            ldsm4(bh, smb + PG_B + swz((uint32_t)(wn*32 + nb*16 + lrow)*128 + kb));
            #pragma unroll
            for (int mb = 0; mb < 2; ++mb) {
                mma16816(acc[mb][nb*2],   ah[mb], bh[0], bh[2]);
                mma16816(acc[mb][nb*2+1], ah[mb], bh[1], bh[3]);
            }
        }
    }

    int rbase = r0 + wm*32 + (lane >> 2);
    int cb = wn*32 + (lane & 3)*2;
    #pragma unroll
    for (int mb = 0; mb < 2; ++mb) {
        #pragma unroll
        for (int nn = 0; nn < 4; ++nn) {
            int col = cb + nn*8;
            float b0 = bias[col], b1 = bias[col+1];
            size_t ra = (size_t)(rbase + mb*16) * HD + col;
            size_t rb = (size_t)(rbase + mb*16 + 8) * HD + col;
            *(unsigned*)(g_posb + ra) = pk2(acc[mb][nn][0] + b0, acc[mb][nn][1] + b1);
            *(unsigned*)(g_posb + rb) = pk2(acc[mb][nn][2] + b0, acc[mb][nn][3] + b1);
        }
    }
}

// ---------------- fused attention ----------------
__global__ void __launch_bounds__(128) k_attn(float* __restrict__ attn_out) {
    __shared__ int   idx_s[16];
    __shared__ float pos_s[16][68];
    __shared__ float k_s[16][260];
    __shared__ float q_s[256];
    __shared__ float logit_s[64];
    __shared__ float attn_s[64];
    int t  = threadIdx.x;
    int gp = blockIdx.x;
    int b  = gp >> 13, n = gp & (NPTS-1);

    if (t < 16) idx_s[t] = g_knn[gp*KNBR + t];
    if (t < 64) ((float4*)q_s)[t] = ((const float4*)(g_qkv + (size_t)gp * 768))[t];
    {
        const uint2* ps = (const uint2*)(g_posb + (size_t)gp * KNBR * HD);
        #pragma unroll
        for (int e = t; e < 256; e += 128) {
            int jj = e >> 4, cc = e & 15;
            uint2 u = ps[e];
            float2 f0 = __bfloat1622float2(*(__nv_bfloat162*)&u.x);
            float2 f1 = __bfloat1622float2(*(__nv_bfloat162*)&u.y);
            *(float4*)&pos_s[jj][cc*4] = make_float4(f0.x, f0.y, f1.x, f1.y);
        }
    }
    __syncthreads();
    #pragma unroll
    for (int e = t; e < 1024; e += 128) {
        int jj = e >> 6, cc = e & 63;
        size_t rowb = ((size_t)b * NPTS + idx_s[jj]) * 768;
        *(float4*)&k_s[jj][cc*4] = *(const float4*)(g_qkv + rowb + 256 + cc*4);
    }
    __syncthreads();
    {
        int p = t >> 1, half = t & 1;
        int jj = p & 15, h = p >> 4;
        float s = 0.f;
        int cbs = half * 32;
        #pragma unroll
        for (int c = 0; c < 32; ++c) {
            int cc = cbs + c;
            s = fmaf(q_s[h*64+cc], k_s[jj][h*64+cc] + pos_s[jj][cc], s);
        }
        s += __shfl_xor_sync(~0u, s, 1);
        if (half == 0) logit_s[h*16 + jj] = s * 0.125f;
    }
    __syncthreads();
    if (t < 64) {
        int h2 = t >> 4, j2 = t & 15;
        float l = logit_s[t];
        float mx = l;
        #pragma unroll
        for (int o = 8; o; o >>= 1) mx = fmaxf(mx, __shfl_xor_sync(~0u, mx, o));
        float ex = expf(l - mx);
        float sum = ex;
        #pragma unroll
        for (int o = 8; o; o >>= 1) sum += __shfl_xor_sync(~0u, sum, o);
        float a = ex / sum;
        attn_s[t] = a;
        attn_out[(((size_t)b*NH + h2) * NPTS + n) * KNBR + j2] = a;
    }
    __syncthreads();
    #pragma unroll
    for (int ee = 0; ee < 2; ++ee) {
        int e = t + ee*128;
        int h3 = e >> 6, c = e & 63;
        float s = 0.f;
        #pragma unroll
        for (int j = 0; j < 16; ++j) {
            float v = g_qkv[((size_t)b * NPTS + idx_s[j]) * 768 + 512 + e];
            s = fmaf(attn_s[h3*16 + j], v + pos_s[j][c], s);
        }
        float hs = rndbf(s);
        g_mid_h[(size_t)gp * DOUT + e] = __float2bfloat16_rn(s);
        g_mid_l[(size_t)gp * DOUT + e] = __float2bfloat16_rn(s - hs);
    }
}

// ---------------- final: LN(fc2)*g2+b2 + lnq -> out ----------------
__global__ void k_final(const float* __restrict__ g2, const float* __restrict__ b2,
                        float* __restrict__ out) {
    int warp = (blockIdx.x * blockDim.x + threadIdx.x) >> 5;
    int lane = threadIdx.x & 31;
    const float4* row = (const float4*)(g_fc2 + (size_t)warp * DOUT);
    float4 v0 = row[lane*2], v1 = row[lane*2+1];
    float s = v0.x+v0.y+v0.z+v0.w + v1.x+v1.y+v1.z+v1.w;
    #pragma unroll
    for (int o = 16; o; o >>= 1) s += __shfl_xor_sync(~0u, s, o);
    float mu = s * (1.f/256.f);
    float d0x=v0.x-mu, d0y=v0.y-mu, d0z=v0.z-mu, d0w=v0.w-mu;
    float d1x=v1.x-mu, d1y=v1.y-mu, d1z=v1.z-mu, d1w=v1.w-mu;
    float s2 = d0x*d0x+d0y*d0y+d0z*d0z+d0w*d0w + d1x*d1x+d1y*d1y+d1z*d1z+d1w*d1w;
    #pragma unroll
    for (int o = 16; o; o >>= 1) s2 += __shfl_xor_sync(~0u, s2, o);
    float rs = rsqrtf(s2 * (1.f/256.f) + 1e-5f);
    float4 gA = ((const float4*)g2)[lane*2],  gB = ((const float4*)g2)[lane*2+1];
    float4 bA = ((const float4*)b2)[lane*2],  bB = ((const float4*)b2)[lane*2+1];
    const float4* lq = (const float4*)(g_lnq + (size_t)warp * DOUT);
    float4 qA = lq[lane*2], qB = lq[lane*2+1];
    float4 oA, oB;
    oA.x = d0x*rs*gA.x + bA.x + qA.x; oA.y = d0y*rs*gA.y + bA.y + qA.y;
    oA.z = d0z*rs*gA.z + bA.z + qA.z; oA.w = d0w*rs*gA.w + bA.w + qA.w;
    oB.x = d1x*rs*gB.x + bB.x + qB.x; oB.y = d1y*rs*gB.y + bB.y + qB.y;
    oB.z = d1z*rs*gB.z + bB.z + qB.z; oB.w = d1w*rs*gB.w + bB.w + qB.w;
    float4* dst = (float4*)(out + (size_t)warp * DOUT);
    dst[lane*2]   = oA;
    dst[lane*2+1] = oB;
}

// ---------------- host launcher ----------------
extern "C" void kernel_launch(void* const* d_in, const int* in_sizes, int n_in,
                              void* d_out, int out_size) {
    const float* xyz      = (const float*)d_in[0];
    const float* features = (const float*)d_in[1];
    const float* Wq  = (const float*)d_in[2];
    const float* bq  = (const float*)d_in[3];
    const float* Wk  = (const float*)d_in[4];
    const float* bk  = (const float*)d_in[5];
    const float* Wv  = (const float*)d_in[6];
    const float* bv  = (const float*)d_in[7];
    const float* Wp1 = (const float*)d_in[8];
    const float* bp1 = (const float*)d_in[9];
    const float* Wp2 = (const float*)d_in[10];
    const float* bp2 = (const float*)d_in[11];
    const float* Wf1 = (const float*)d_in[12];
    const float* bf1 = (const float*)d_in[13];
    const float* Wf2 = (const float*)d_in[14];
    const float* bf2 = (const float*)d_in[15];
    const float* g1  = (const float*)d_in[16];
    const float* b1  = (const float*)d_in[17];
    const float* g2  = (const float*)d_in[18];
    const float* b2  = (const float*)d_in[19];

    float* out      = (float*)d_out;
    float* attn_out = out + (size_t)ROWS * DOUT;

    #define SYM(p, s) float* p; cudaGetSymbolAddress((void**)&p, s)
    #define SYMB(p, s) __nv_bfloat16* p; cudaGetSymbolAddress((void**)&p, s)
    SYMB(p_feat_h, g_feat_h); SYMB(p_feat_l, g_feat_l);
    SYMB(p_lnf_h,  g_lnf_h);  SYMB(p_lnf_l,  g_lnf_l);
    SYM(p_qkv, g_qkv); SYM(p_lnq, g_lnq); SYM(p_fc2, g_fc2);
    SYMB(p_mid_h, g_mid_h); SYMB(p_mid_l, g_mid_l);
    SYMB(p_fc1_h, g_fc1_h); SYMB(p_fc1_l, g_fc1_l);
    SYMB(p_wqkvT_h, g_wqkvT_h); SYMB(p_wqkvT_l, g_wqkvT_l);
    SYMB(p_wf1T_h, g_wf1T_h);   SYMB(p_wf1T_l, g_wf1T_l);
    SYMB(p_wf2T_h, g_wf2T_h);   SYMB(p_wf2T_l, g_wf2T_l);
    SYM(p_bqkv, g_bqkv);

    static cudaStream_t s2 = nullptr;
    static cudaEvent_t evPrep = nullptr, evSide = nullptr, evLnq = nullptr;
    static bool attr_done = false;
    if (!attr_done) {
        cudaFuncSetAttribute(k_mgemm, cudaFuncAttributeMaxDynamicSharedMemorySize, MG_SMEM);
        cudaFuncSetAttribute(k_knn2,  cudaFuncAttributeMaxDynamicSharedMemorySize, SMEM_KNN);
        cudaFuncSetAttribute(k_pgemm, cudaFuncAttributeMaxDynamicSharedMemorySize, SMEM_PG);
        cudaStreamCreateWithFlags(&s2, cudaStreamNonBlocking);
        cudaEventCreateWithFlags(&evPrep, cudaEventDisableTiming);
        cudaEventCreateWithFlags(&evSide, cudaEventDisableTiming);
        cudaEventCreateWithFlags(&evLnq, cudaEventDisableTiming);
        attr_done = true;
    }

    // 1: merged prep (default)
    k_prep<<<PREP_BLOCKS, 256>>>(xyz, features, Wq, Wk, Wv, Wp2, Wf1, Wf2, g1, b1, bq, bk, bv);
    cudaEventRecord(evPrep, 0);

    // side branch (s2): knn -> pos, then lnq (only needed by k_final)
    cudaStreamWaitEvent(s2, evPrep, 0);
    {
        dim3 kg(NPTS/16, BATCH);
        k_knn2<<<kg, 512, SMEM_KNN, s2>>>();
    }
    k_pgemm<<<NROWS/128, 256, SMEM_PG, s2>>>(Wp1, bp1, bp2);
    cudaEventRecord(evSide, s2);

    // main branch (default): qkv GEMM
    {
        dim3 g(ROWS/128, 12);
        k_mgemm<<<g, 128, MG_SMEM>>>(p_feat_h, p_feat_l, p_wqkvT_h, p_wqkvT_l,
                                     p_bqkv, p_qkv, nullptr, nullptr, DIM, 768, 0);
    }

    // lnq GEMM on side stream (overlaps with attn/fc)
    {
        dim3 g(ROWS/128, 4);
        k_mgemm<<<g, 128, MG_SMEM, s2>>>(p_lnf_h, p_lnf_l, p_wqkvT_h, p_wqkvT_l,
                                         bq, p_lnq, nullptr, nullptr, DIM, DOUT, 0);
    }
    cudaEventRecord(evLnq, s2);

    // join (knn+pos ready), then attention
    cudaStreamWaitEvent(0, evSide, 0);
    k_attn<<<ROWS, 128>>>(attn_out);

    // fc1, fc2
    {
        dim3 g(ROWS/128, 4);
        k_mgemm<<<g, 128, MG_SMEM>>>(p_mid_h, p_mid_l, p_wf1T_h, p_wf1T_l,
                                     bf1, nullptr, p_fc1_h, p_fc1_l, DOUT, DOUT, 1);
        k_mgemm<<<g, 128, MG_SMEM>>>(p_fc1_h, p_fc1_l, p_wf2T_h, p_wf2T_l,
                                     bf2, p_fc2, nullptr, nullptr, DOUT, DOUT, 0);
    }

    // final LN + residual (needs lnq)
    cudaStreamWaitEvent(0, evLnq, 0);
    k_final<<<ROWS/8, 256>>>(g2, b2, out);
}

// round 13
// speedup vs baseline: 1.0185x; 1.0185x over previous
#include <cuda_runtime.h>
#include <cuda_bf16.h>
#include <cstdint>
#include <math.h>

#define BATCH 4
#define NPTS  8192
#define DIM   128
#define DOUT  256
#define NH    4
#define HD    64
#define KNBR  16
#define ROWS  (BATCH*NPTS)          // 32768
#define NROWS (BATCH*NPTS*KNBR)     // 524288

// ---------------- scratch (device globals; no runtime alloc) ----------------
__device__ float4 g_xyzw[ROWS];
__device__ int    g_knn[NROWS];
__device__ __nv_bfloat16 g_feat_h[ROWS*DIM];
__device__ __nv_bfloat16 g_feat_l[ROWS*DIM];
__device__ __nv_bfloat16 g_lnf_h[ROWS*DIM];
__device__ __nv_bfloat16 g_lnf_l[ROWS*DIM];
__device__ float  g_qf[(size_t)ROWS*DOUT];            // q fp32
__device__ __nv_bfloat16 g_kvb[(size_t)ROWS*DOUT];    // k bf16
__device__ float  g_vf[(size_t)ROWS*DOUT];            // v fp32
__device__ float  g_lnq[ROWS*DOUT];
__device__ __nv_bfloat16 g_posb[(size_t)NROWS*HD];
__device__ __nv_bfloat16 g_mid_h[ROWS*DOUT];
__device__ __nv_bfloat16 g_mid_l[ROWS*DOUT];
__device__ __nv_bfloat16 g_fc1_h[ROWS*DOUT];
__device__ __nv_bfloat16 g_fc1_l[ROWS*DOUT];
__device__ float  g_fc2[ROWS*DOUT];
__device__ __nv_bfloat16 g_wqkvT_h[768*DIM];
__device__ __nv_bfloat16 g_wqkvT_l[768*DIM];
__device__ __nv_bfloat16 g_wp2T_h[HD*HD];
__device__ __nv_bfloat16 g_wf1T_h[DOUT*DOUT];
__device__ __nv_bfloat16 g_wf1T_l[DOUT*DOUT];
__device__ __nv_bfloat16 g_wf2T_h[DOUT*DOUT];
__device__ __nv_bfloat16 g_wf2T_l[DOUT*DOUT];
__device__ float g_bqkv[768];

// ---------------- small helpers ----------------
__device__ __forceinline__ unsigned pk2(float a, float b) {
    __nv_bfloat162 t = __floats2bfloat162_rn(a, b);
    return *(unsigned*)&t;
}
__device__ __forceinline__ float rndbf(float x) {
    return __bfloat162float(__float2bfloat16_rn(x));
}
__device__ __forceinline__ uint32_t smem_u32(const void* p) {
    uint32_t a;
    asm("{ .reg .u64 t; cvta.to.shared.u64 t, %1; cvt.u32.u64 %0, t; }" : "=r"(a) : "l"(p));
    return a;
}
__device__ __forceinline__ uint32_t swz(uint32_t x) { return x ^ ((x >> 3) & 0x70); }

__device__ __forceinline__ void ldsm4(uint32_t* r, uint32_t addr) {
    asm volatile("ldmatrix.sync.aligned.m8n8.x4.shared.b16 {%0,%1,%2,%3}, [%4];"
        : "=r"(r[0]), "=r"(r[1]), "=r"(r[2]), "=r"(r[3]) : "r"(addr));
}
__device__ __forceinline__ void mma16816(float* c, const uint32_t* a, uint32_t b0, uint32_t b1) {
    asm volatile("mma.sync.aligned.m16n8k16.row.col.f32.bf16.bf16.f32 "
        "{%0,%1,%2,%3}, {%4,%5,%6,%7}, {%8,%9}, {%0,%1,%2,%3};"
        : "+f"(c[0]), "+f"(c[1]), "+f"(c[2]), "+f"(c[3])
        : "r"(a[0]), "r"(a[1]), "r"(a[2]), "r"(a[3]), "r"(b0), "r"(b1));
}
#define CP16(dst, src) asm volatile("cp.async.cg.shared.global [%0], [%1], 16;" :: "r"(dst), "l"(src))
#define CP_COMMIT()    asm volatile("cp.async.commit_group;" ::: "memory")
#define CP_WAIT1()     asm volatile("cp.async.wait_group 1;" ::: "memory")

// ---------------- merged prep ----------------
#define PREP_BLOCKS 4284

__device__ __forceinline__ void tileT(const float* __restrict__ W,
                                      __nv_bfloat16* Th, __nv_bfloat16* Tl,
                                      int Kd, int Nd, int k0, int n0,
                                      int tid, float (*ts)[65]) {
    #pragma unroll
    for (int i = 0; i < 16; ++i) {
        int e = tid + i*256;
        int r = e >> 6, c = e & 63;
        ts[r][c] = W[(size_t)(k0 + r) * Nd + n0 + c];
    }
    __syncthreads();
    #pragma unroll
    for (int i = 0; i < 16; ++i) {
        int e = tid + i*256;
        int kk = e & 63, nn = e >> 6;
        float x = ts[kk][nn];
        size_t o = (size_t)(n0 + nn) * Kd + k0 + kk;
        float hx = rndbf(x);
        Th[o] = __float2bfloat16_rn(x);
        if (Tl) Tl[o] = __float2bfloat16_rn(x - hx);
    }
}

__global__ void __launch_bounds__(256) k_prep(
    const float* __restrict__ xyz, const float* __restrict__ features,
    const float* __restrict__ Wq, const float* __restrict__ Wk, const float* __restrict__ Wv,
    const float* __restrict__ Wp2, const float* __restrict__ Wf1, const float* __restrict__ Wf2,
    const float* __restrict__ g1, const float* __restrict__ b1,
    const float* __restrict__ bq, const float* __restrict__ bk, const float* __restrict__ bv)
{
    __shared__ float ts[64][65];
    int bid = blockIdx.x, tid = threadIdx.x;
    if (bid < 128) {
        int i = bid * 256 + tid;
        float x = xyz[i*3+0], y = xyz[i*3+1], z = xyz[i*3+2];
        g_xyzw[i] = make_float4(x, y, z, x*x + y*y + z*z);
    } else if (bid < 4224) {
        int row = (bid - 128) * 8 + (tid >> 5);
        int lane = tid & 31;
        float4 v = ((const float4*)(features + (size_t)row * DIM))[lane];
        int idx = row*32 + lane;
        {
            float hx = rndbf(v.x), hy = rndbf(v.y), hz = rndbf(v.z), hw = rndbf(v.w);
            ((uint2*)g_feat_h)[idx] = make_uint2(pk2(v.x, v.y), pk2(v.z, v.w));
            ((uint2*)g_feat_l)[idx] = make_uint2(pk2(v.x-hx, v.y-hy), pk2(v.z-hz, v.w-hw));
        }
        float s = v.x + v.y + v.z + v.w;
        #pragma unroll
        for (int o = 16; o; o >>= 1) s += __shfl_xor_sync(~0u, s, o);
        float mu = s * (1.f/128.f);
        float dx = v.x-mu, dy = v.y-mu, dz = v.z-mu, dw = v.w-mu;
        float s2 = dx*dx + dy*dy + dz*dz + dw*dw;
        #pragma unroll
        for (int o = 16; o; o >>= 1) s2 += __shfl_xor_sync(~0u, s2, o);
        float rs = rsqrtf(s2 * (1.f/128.f) + 1e-5f);
        float4 gg = ((const float4*)g1)[lane];
        float4 bb = ((const float4*)b1)[lane];
        float rx = dx*rs*gg.x + bb.x, ry = dy*rs*gg.y + bb.y;
        float rz = dz*rs*gg.z + bb.z, rw = dw*rs*gg.w + bb.w;
        float hx = rndbf(rx), hy = rndbf(ry), hz = rndbf(rz), hw = rndbf(rw);
        ((uint2*)g_lnf_h)[idx] = make_uint2(pk2(rx, ry), pk2(rz, rw));
        ((uint2*)g_lnf_l)[idx] = make_uint2(pk2(rx-hx, ry-hy), pk2(rz-hz, rw-hw));
    } else if (bid < 4248) {
        int b2 = bid - 4224;
        int m = b2 >> 3, tt = b2 & 7;
        const float* W = m == 0 ? Wq : (m == 1 ? Wk : Wv);
        tileT(W, g_wqkvT_h + m*256*DIM, g_wqkvT_l + m*256*DIM,
              DIM, DOUT, (tt & 1)*64, (tt >> 1)*64, tid, ts);
    } else if (bid < 4249) {
        tileT(Wp2, g_wp2T_h, nullptr, HD, HD, 0, 0, tid, ts);
    } else if (bid < 4265) {
        int b2 = bid - 4249;
        tileT(Wf1, g_wf1T_h, g_wf1T_l, DOUT, DOUT, (b2 & 3)*64, (b2 >> 2)*64, tid, ts);
    } else if (bid < 4281) {
        int b2 = bid - 4265;
        tileT(Wf2, g_wf2T_h, g_wf2T_l, DOUT, DOUT, (b2 & 3)*64, (b2 >> 2)*64, tid, ts);
    } else {
        int t = (bid - 4281) * 256 + tid;
        if (t < 256)      g_bqkv[t] = bq[t];
        else if (t < 512) g_bqkv[t] = bk[t-256];
        else              g_bqkv[t] = bv[t-512];
    }
}

// ---------------- KNN ----------------
#define KNN_CAP 256
#define SMEM_KNN (32768 + 16*KNN_CAP*8)

__global__ void __launch_bounds__(512) k_knn2() {
    extern __shared__ char sk[];
    float4* tile = (float4*)sk;
    float*  bkey = (float*)(sk + 32768);
    int*    bidx = (int*)(sk + 32768 + 16*KNN_CAP*4);
    int t = threadIdx.x, lane = t & 31, w = t >> 5;
    int b = blockIdx.y;
    int q = blockIdx.x * 16 + w;
    const float INF = 3.402823e38f;

    float4 me = g_xyzw[b*NPTS + q];
    float qx2 = -2.f*me.x, qy2 = -2.f*me.y, qz2 = -2.f*me.z;

    float T = 0.f;
    int base = 0;
    float* mk = bkey + w*KNN_CAP;
    int*   mi = bidx + w*KNN_CAP;

    for (int ti = 0; ti < 4; ++ti) {
        __syncthreads();
        for (int i = t; i < 2048; i += 512)
            tile[i] = g_xyzw[b*NPTS + ti*2048 + i];
        __syncthreads();

        if (ti == 0) {
            float mn = INF;
            #pragma unroll 8
            for (int i = 0; i < 64; ++i) {
                float4 p = tile[i*32 + lane];
                float d = fmaf(qx2,p.x,fmaf(qy2,p.y,fmaf(qz2,p.z,p.w)));
                mn = fminf(mn, d);
            }
            float v = mn;
            #pragma unroll
            for (int k = 2; k <= 32; k <<= 1) {
                #pragma unroll
                for (int j = k >> 1; j > 0; j >>= 1) {
                    float o = __shfl_xor_sync(~0u, v, j);
                    bool up = ((lane & k) == 0);
                    bool lower = ((lane & j) == 0);
                    v = (lower == up) ? fminf(v, o) : fmaxf(v, o);
                }
            }
            T = __shfl_sync(~0u, v, 15);
        }

        #pragma unroll 4
        for (int c = 0; c < 64; ++c) {
            int j = c*32 + lane;
            float4 p = tile[j];
            float d = fmaf(qx2,p.x,fmaf(qy2,p.y,fmaf(qz2,p.z,p.w)));
            bool pass = (d <= T);
            unsigned m = __ballot_sync(~0u, pass);
            if (pass) {
                int pos = base + __popc(m & ((1u << lane) - 1u));
                if (pos < KNN_CAP) { mk[pos] = d; mi[pos] = ti*2048 + j; }
            }
            base += __popc(m);
        }
    }
    if (base > KNN_CAP) base = KNN_CAP;
    __syncwarp();

    size_t ob = ((size_t)b*NPTS + q) * KNBR;
    for (int r = 0; r < KNBR; ++r) {
        float bk = INF; int bi = 0x7fffffff; int bp = -1;
        for (int i = lane; i < base; i += 32) {
            float kk = mk[i];
            int   ii = mi[i];
            if (kk < bk || (kk == bk && ii < bi)) { bk = kk; bi = ii; bp = i; }
        }
        #pragma unroll
        for (int o = 16; o; o >>= 1) {
            float ok = __shfl_xor_sync(~0u, bk, o);
            int   oi = __shfl_xor_sync(~0u, bi, o);
            int   op = __shfl_xor_sync(~0u, bp, o);
            if (ok < bk || (ok == bk && oi < bi)) { bk = ok; bi = oi; bp = op; }
        }
        if (lane == 0) {
            g_knn[ob + r] = bi;
            if (bp >= 0) mk[bp] = INF;
        }
        __syncwarp();
    }
}

// ---------------- mma GEMM: CTA 128x64, warp 32x32, 2 CTAs/SM, cp.async 2-stage ----------------
// kvmode: c0<256 -> q fp32; 256<=c0<512 -> k bf16; c0>=512 -> v fp32
#define MG_STGB  24576
#define MG_SMEM  (2*MG_STGB)

__global__ void __launch_bounds__(256, 2) k_mgemm(
    const __nv_bfloat16* __restrict__ Ah, const __nv_bfloat16* __restrict__ Al,
    const __nv_bfloat16* __restrict__ Bh, const __nv_bfloat16* __restrict__ Bl,
    const float* __restrict__ bias,
    float* Cf, __nv_bfloat16* Ch, __nv_bfloat16* Cl,
    int K, int ldc, int relu, int kvmode)
{
    extern __shared__ char sm[];
    uint32_t smb = smem_u32(sm);
    int t = threadIdx.x, lane = t & 31, w = t >> 5;
    int wm = w & 3, wn = w >> 2;
    int c0 = blockIdx.y * 64;
    int r0 = blockIdx.x * 128;
    int nch = K >> 5;

    float acc[2][4][4];
    #pragma unroll
    for (int i = 0; i < 2; ++i)
        #pragma unroll
        for (int j = 0; j < 4; ++j)
            #pragma unroll
            for (int e = 0; e < 4; ++e) acc[i][j][e] = 0.f;

    int lrow = lane & 15;
    int lcb  = (lane >> 4) * 16;

    auto issue = [&](int c, int stg) {
        int kc = c * 32;
        uint32_t Ab = smb + stg*MG_STGB;
        uint32_t Bb = Ab + 16384;
        #pragma unroll
        for (int i = 0; i < 4; ++i) {
            int e = t + i*256;
            int row = e >> 3, seg = e & 7;
            const __nv_bfloat16* src = (seg < 4 ? Ah : Al) + (size_t)(r0+row)*K + kc + (seg & 3)*8;
            CP16(Ab + swz((uint32_t)row*128 + seg*16), src);
        }
        #pragma unroll
        for (int i = 0; i < 2; ++i) {
            int e = t + i*256;
            int row = e >> 3, seg = e & 7;
            const __nv_bfloat16* src = (seg < 4 ? Bh : Bl) + (size_t)(c0+row)*K + kc + (seg & 3)*8;
            CP16(Bb + swz((uint32_t)row*128 + seg*16), src);
        }
    };

    issue(0, 0); CP_COMMIT();
    issue(1, 1); CP_COMMIT();

    for (int c = 0; c < nch; ++c) {
        CP_WAIT1();
        __syncthreads();
        uint32_t Ab = smb + (c & 1)*MG_STGB;
        uint32_t Bb = Ab + 16384;
        #pragma unroll
        for (int s = 0; s < 2; ++s) {
            int kb = s*32 + lcb;
            uint32_t ah[2][4], al[2][4];
            #pragma unroll
            for (int mb = 0; mb < 2; ++mb) {
                uint32_t ro = (uint32_t)(wm*32 + mb*16 + lrow)*128;
                ldsm4(ah[mb], Ab + swz(ro + kb));
                ldsm4(al[mb], Ab + swz(ro + 64 + kb));
            }
            #pragma unroll
            for (int nb = 0; nb < 2; ++nb) {
                uint32_t bh[4], bl[4];
                uint32_t ro = (uint32_t)(wn*32 + nb*16 + lrow)*128;
                ldsm4(bh, Bb + swz(ro + kb));
                ldsm4(bl, Bb + swz(ro + 64 + kb));
                #pragma unroll
                for (int mb = 0; mb < 2; ++mb) {
                    float* cA = acc[mb][nb*2];
                    float* cB = acc[mb][nb*2+1];
                    mma16816(cA, ah[mb], bh[0], bh[2]);
                    mma16816(cB, ah[mb], bh[1], bh[3]);
                    mma16816(cA, ah[mb], bl[0], bl[2]);
                    mma16816(cB, ah[mb], bl[1], bl[3]);
                    mma16816(cA, al[mb], bh[0], bh[2]);
                    mma16816(cB, al[mb], bh[1], bh[3]);
                }
            }
        }
        __syncthreads();
        if (c + 2 < nch) issue(c + 2, c & 1);
        CP_COMMIT();
    }

    int rbase = r0 + wm*32 + (lane >> 2);
    int cb = c0 + wn*32 + (lane & 3)*2;
    #pragma unroll
    for (int mb = 0; mb < 2; ++mb) {
        #pragma unroll
        for (int nn = 0; nn < 4; ++nn) {
            int col = cb + nn*8;
            float b0 = bias[col], b1 = bias[col+1];
            float v0 = acc[mb][nn][0] + b0, v1 = acc[mb][nn][1] + b1;
            float v2 = acc[mb][nn][2] + b0, v3 = acc[mb][nn][3] + b1;
            if (relu) {
                v0 = fmaxf(v0, 0.f); v1 = fmaxf(v1, 0.f);
                v2 = fmaxf(v2, 0.f); v3 = fmaxf(v3, 0.f);
            }
            int ra_row = rbase + mb*16, rb_row = rbase + mb*16 + 8;
            if (kvmode) {
                if (c0 < 256) {
                    *(float2*)(g_qf + (size_t)ra_row * DOUT + col) = make_float2(v0, v1);
                    *(float2*)(g_qf + (size_t)rb_row * DOUT + col) = make_float2(v2, v3);
                } else if (c0 < 512) {
                    int kc2 = col - 256;
                    *(unsigned*)(g_kvb + (size_t)ra_row * DOUT + kc2) = pk2(v0, v1);
                    *(unsigned*)(g_kvb + (size_t)rb_row * DOUT + kc2) = pk2(v2, v3);
                } else {
                    int vc2 = col - 512;
                    *(float2*)(g_vf + (size_t)ra_row * DOUT + vc2) = make_float2(v0, v1);
                    *(float2*)(g_vf + (size_t)rb_row * DOUT + vc2) = make_float2(v2, v3);
                }
            } else {
                size_t ra = (size_t)ra_row * ldc + col;
                size_t rb = (size_t)rb_row * ldc + col;
                if (Cf) {
                    *(float2*)(Cf + ra) = make_float2(v0, v1);
                    *(float2*)(Cf + rb) = make_float2(v2, v3);
                }
                if (Ch) {
                    float h0 = rndbf(v0), h1 = rndbf(v1), h2 = rndbf(v2), h3 = rndbf(v3);
                    *(unsigned*)(Ch + ra) = pk2(v0, v1);
                    *(unsigned*)(Cl + ra) = pk2(v0-h0, v1-h1);
                    *(unsigned*)(Ch + rb) = pk2(v2, v3);
                    *(unsigned*)(Cl + rb) = pk2(v2-h2, v3-h3);
                }
            }
        }
    }
}

// ---------------- fused pos GEMM: smem Wp1, float4 xyzw, bf16 out ----------------
#define PG_A 0
#define PG_B 16384
#define PG_W 24576
#define SMEM_PG (24576 + 1024)

__global__ void __launch_bounds__(256) k_pgemm(
    const float* __restrict__ Wp1, const float* __restrict__ bp1,
    const float* __restrict__ bias)
{
    extern __shared__ char sm[];
    uint32_t smb = smem_u32(sm);
    float* ws = (float*)(sm + PG_W);
    int t = threadIdx.x, lane = t & 31, w = t >> 5;
    int wm = w & 3, wn = w >> 2;
    int r0 = blockIdx.x * 128;

    if (t < 192) ws[t] = Wp1[t];
    else ws[t] = bp1[t - 192];
    #pragma unroll 2
    for (int e = t; e < 512; e += 256) {
        int row = e >> 3, vo = e & 7;
        *(uint4*)(sm + PG_B + swz(row*128 + vo*16)) = *(const uint4*)(g_wp2T_h + row*64 + vo*8);
    }
    __syncthreads();

    {
        int row = t >> 1, ch = t & 1;
        int rr = r0 + row;
        int b = rr >> 17, n = (rr >> 4) & (NPTS - 1);
        int idx = g_knn[rr];
        float4 nbp = g_xyzw[(b << 13) + idx];
        float4 ctp = g_xyzw[(b << 13) + n];
        float rx = nbp.x - ctp.x, ry = nbp.y - ctp.y, rz = nbp.z - ctp.z;
        uint32_t hp[16];
        #pragma unroll
        for (int cc = 0; cc < 32; cc += 2) {
            int c = ch*32 + cc;
            float v0 = fmaf(rx, ws[c],   fmaf(ry, ws[64+c],   fmaf(rz, ws[128+c],   ws[192+c])));
            float v1 = fmaf(rx, ws[c+1], fmaf(ry, ws[64+c+1], fmaf(rz, ws[128+c+1], ws[192+c+1])));
            hp[cc>>1] = pk2(fmaxf(v0, 0.f), fmaxf(v1, 0.f));
        }
        uint32_t rbyte = (uint32_t)row*128 + ch*64;
        #pragma unroll
        for (int i = 0; i < 4; ++i)
            *(uint4*)(sm + PG_A + swz(rbyte + i*16)) = *(uint4*)&hp[i*4];
    }
    __syncthreads();

    float acc[2][4][4];
    #pragma unroll
    for (int i = 0; i < 2; ++i)
        #pragma unroll
        for (int j = 0; j < 4; ++j)
            #pragma unroll
            for (int e = 0; e < 4; ++e) acc[i][j][e] = 0.f;
    int lrow = lane & 15, lcolb = (lane >> 4) * 16;
    #pragma unroll
    for (int s = 0; s < 4; ++s) {
        int kb = s*32 + lcolb;
        uint32_t ah[2][4];
        #pragma unroll
        for (int mb = 0; mb < 2; ++mb)
            ldsm4(ah[mb], smb + PG_A + swz((uint32_t)(wm*32 + mb*16 + lrow)*128 + kb));
        #pragma unroll
        for (int nb = 0; nb < 2; ++nb) {
            uint32_t bh[4];
            ldsm4(bh, smb + PG_B + swz((uint32_t)(wn*32 + nb*16 + lrow)*128 + kb));
            #pragma unroll
            for (int mb = 0; mb < 2; ++mb) {
                mma16816(acc[mb][nb*2],   ah[mb], bh[0], bh[2]);
                mma16816(acc[mb][nb*2+1], ah[mb], bh[1], bh[3]);
            }
        }
    }

    int rbase = r0 + wm*32 + (lane >> 2);
    int cb = wn*32 + (lane & 3)*2;
    #pragma unroll
    for (int mb = 0; mb < 2; ++mb) {
        #pragma unroll
        for (int nn = 0; nn < 4; ++nn) {
            int col = cb + nn*8;
            float b0 = bias[col], b1 = bias[col+1];
            size_t ra = (size_t)(rbase + mb*16) * HD + col;
            size_t rb = (size_t)(rbase + mb*16 + 8) * HD + col;
            *(unsigned*)(g_posb + ra) = pk2(acc[mb][nn][0] + b0, acc[mb][nn][1] + b1);
            *(unsigned*)(g_posb + rb) = pk2(acc[mb][nn][2] + b0, acc[mb][nn][3] + b1);
        }
    }
}

// ---------------- fused attention: bf16 k gather, fp32 v ----------------
__global__ void __launch_bounds__(128) k_attn(float* __restrict__ attn_out) {
    __shared__ int   idx_s[16];
    __shared__ float pos_s[16][68];
    __shared__ float k_s[16][260];
    __shared__ float q_s[256];
    __shared__ float logit_s[64];
    __shared__ float attn_s[64];
    int t  = threadIdx.x;
    int gp = blockIdx.x;
    int b  = gp >> 13, n = gp & (NPTS-1);

    if (t < 16) idx_s[t] = g_knn[gp*KNBR + t];
    if (t < 64) ((float4*)q_s)[t] = ((const float4*)(g_qf + (size_t)gp * DOUT))[t];
    {
        const uint2* ps = (const uint2*)(g_posb + (size_t)gp * KNBR * HD);
        #pragma unroll
        for (int e = t; e < 256; e += 128) {
            int jj = e >> 4, cc = e & 15;
            uint2 u = ps[e];
            float2 f0 = __bfloat1622float2(*(__nv_bfloat162*)&u.x);
            float2 f1 = __bfloat1622float2(*(__nv_bfloat162*)&u.y);
            *(float4*)&pos_s[jj][cc*4] = make_float4(f0.x, f0.y, f1.x, f1.y);
        }
    }
    __syncthreads();
    // gather bf16 k: 256 bf16 per row = 64 uint2 per row, 16 rows = 1024 uint2
    #pragma unroll
    for (int e = t; e < 1024; e += 128) {
        int jj = e >> 6, uu = e & 63;
        size_t rowb = ((size_t)b * NPTS + idx_s[jj]) * DOUT;
        uint2 u = ((const uint2*)(g_kvb + rowb))[uu];
        float2 f0 = __bfloat1622float2(*(__nv_bfloat162*)&u.x);
        float2 f1 = __bfloat1622float2(*(__nv_bfloat162*)&u.y);
        *(float4*)&k_s[jj][uu*4] = make_float4(f0.x, f0.y, f1.x, f1.y);
    }
    __syncthreads();
    {
        int p = t >> 1, half = t & 1;
        int jj = p & 15, h = p >> 4;
        float s = 0.f;
        int cbs = half * 32;
        #pragma unroll
        for (int c = 0; c < 32; ++c) {
            int cc = cbs + c;
            s = fmaf(q_s[h*64+cc], k_s[jj][h*64+cc] + pos_s[jj][cc], s);
        }
        s += __shfl_xor_sync(~0u, s, 1);
        if (half == 0) logit_s[h*16 + jj] = s * 0.125f;
    }
    __syncthreads();
    if (t < 64) {
        int h2 = t >> 4, j2 = t & 15;
        float l = logit_s[t];
        float mx = l;
        #pragma unroll
        for (int o = 8; o; o >>= 1) mx = fmaxf(mx, __shfl_xor_sync(~0u, mx, o));
        float ex = expf(l - mx);
        float sum = ex;
        #pragma unroll
        for (int o = 8; o; o >>= 1) sum += __shfl_xor_sync(~0u, sum, o);
        float a = ex / sum;
        attn_s[t] = a;
        attn_out[(((size_t)b*NH + h2) * NPTS + n) * KNBR + j2] = a;
    }
    __syncthreads();
    // weighted sum with fp32 v streamed from global
    #pragma unroll
    for (int ee = 0; ee < 2; ++ee) {
        int e = t + ee*128;
        int h3 = e >> 6, c = e & 63;
        float s = 0.f;
        #pragma unroll
        for (int j = 0; j < 16; ++j) {
            float v = g_vf[((size_t)b * NPTS + idx_s[j]) * DOUT + e];
            s = fmaf(attn_s[h3*16 + j], v + pos_s[j][c], s);
        }
        float hs = rndbf(s);
        g_mid_h[(size_t)gp * DOUT + e] = __float2bfloat16_rn(s);
        g_mid_l[(size_t)gp * DOUT + e] = __float2bfloat16_rn(s - hs);
    }
}

// ---------------- final: LN(fc2)*g2+b2 + lnq -> out ----------------
__global__ void k_final(const float* __restrict__ g2, const float* __restrict__ b2,
                        float* __restrict__ out) {
    int warp = (blockIdx.x * blockDim.x + threadIdx.x) >> 5;
    int lane = threadIdx.x & 31;
    const float4* row = (const float4*)(g_fc2 + (size_t)warp * DOUT);
    float4 v0 = row[lane*2], v1 = row[lane*2+1];
    float s = v0.x+v0.y+v0.z+v0.w + v1.x+v1.y+v1.z+v1.w;
    #pragma unroll
    for (int o = 16; o; o >>= 1) s += __shfl_xor_sync(~0u, s, o);
    float mu = s * (1.f/256.f);
    float d0x=v0.x-mu, d0y=v0.y-mu, d0z=v0.z-mu, d0w=v0.w-mu;
    float d1x=v1.x-mu, d1y=v1.y-mu, d1z=v1.z-mu, d1w=v1.w-mu;
    float s2 = d0x*d0x+d0y*d0y+d0z*d0z+d0w*d0w + d1x*d1x+d1y*d1y+d1z*d1z+d1w*d1w;
    #pragma unroll
    for (int o = 16; o; o >>= 1) s2 += __shfl_xor_sync(~0u, s2, o);
    float rs = rsqrtf(s2 * (1.f/256.f) + 1e-5f);
    float4 gA = ((const float4*)g2)[lane*2],  gB = ((const float4*)g2)[lane*2+1];
    float4 bA = ((const float4*)b2)[lane*2],  bB = ((const float4*)b2)[lane*2+1];
    const float4* lq = (const float4*)(g_lnq + (size_t)warp * DOUT);
    float4 qA = lq[lane*2], qB = lq[lane*2+1];
    float4 oA, oB;
    oA.x = d0x*rs*gA.x + bA.x + qA.x; oA.y = d0y*rs*gA.y + bA.y + qA.y;
    oA.z = d0z*rs*gA.z + bA.z + qA.z; oA.w = d0w*rs*gA.w + bA.w + qA.w;
    oB.x = d1x*rs*gB.x + bB.x + qB.x; oB.y = d1y*rs*gB.y + bB.y + qB.y;
    oB.z = d1z*rs*gB.z + bB.z + qB.z; oB.w = d1w*rs*gB.w + bB.w + qB.w;
    float4* dst = (float4*)(out + (size_t)warp * DOUT);
    dst[lane*2]   = oA;
    dst[lane*2+1] = oB;
}

// ---------------- host launcher ----------------
extern "C" void kernel_launch(void* const* d_in, const int* in_sizes, int n_in,
                              void* d_out, int out_size) {
    const float* xyz      = (const float*)d_in[0];
    const float* features = (const float*)d_in[1];
    const float* Wq  = (const float*)d_in[2];
    const float* bq  = (const float*)d_in[3];
    const float* Wk  = (const float*)d_in[4];
    const float* bk  = (const float*)d_in[5];
    const float* Wv  = (const float*)d_in[6];
    const float* bv  = (const float*)d_in[7];
    const float* Wp1 = (const float*)d_in[8];
    const float* bp1 = (const float*)d_in[9];
    const float* Wp2 = (const float*)d_in[10];
    const float* bp2 = (const float*)d_in[11];
    const float* Wf1 = (const float*)d_in[12];
    const float* bf1 = (const float*)d_in[13];
    const float* Wf2 = (const float*)d_in[14];
    const float* bf2 = (const float*)d_in[15];
    const float* g1  = (const float*)d_in[16];
    const float* b1  = (const float*)d_in[17];
    const float* g2  = (const float*)d_in[18];
    const float* b2  = (const float*)d_in[19];

    float* out      = (float*)d_out;
    float* attn_out = out + (size_t)ROWS * DOUT;

    #define SYM(p, s) float* p; cudaGetSymbolAddress((void**)&p, s)
    #define SYMB(p, s) __nv_bfloat16* p; cudaGetSymbolAddress((void**)&p, s)
    SYMB(p_feat_h, g_feat_h); SYMB(p_feat_l, g_feat_l);
    SYMB(p_lnf_h,  g_lnf_h);  SYMB(p_lnf_l,  g_lnf_l);
    SYM(p_lnq, g_lnq); SYM(p_fc2, g_fc2);
    SYMB(p_mid_h, g_mid_h); SYMB(p_mid_l, g_mid_l);
    SYMB(p_fc1_h, g_fc1_h); SYMB(p_fc1_l, g_fc1_l);
    SYMB(p_wqkvT_h, g_wqkvT_h); SYMB(p_wqkvT_l, g_wqkvT_l);
    SYMB(p_wf1T_h, g_wf1T_h);   SYMB(p_wf1T_l, g_wf1T_l);
    SYMB(p_wf2T_h, g_wf2T_h);   SYMB(p_wf2T_l, g_wf2T_l);
    SYM(p_bqkv, g_bqkv);

    static cudaStream_t s2 = nullptr;
    static cudaEvent_t evPrep = nullptr, evSide = nullptr, evLnq = nullptr;
    static bool attr_done = false;
    if (!attr_done) {
        cudaFuncSetAttribute(k_mgemm, cudaFuncAttributeMaxDynamicSharedMemorySize, MG_SMEM);
        cudaFuncSetAttribute(k_knn2,  cudaFuncAttributeMaxDynamicSharedMemorySize, SMEM_KNN);
        cudaFuncSetAttribute(k_pgemm, cudaFuncAttributeMaxDynamicSharedMemorySize, SMEM_PG);
        cudaStreamCreateWithFlags(&s2, cudaStreamNonBlocking);
        cudaEventCreateWithFlags(&evPrep, cudaEventDisableTiming);
        cudaEventCreateWithFlags(&evSide, cudaEventDisableTiming);
        cudaEventCreateWithFlags(&evLnq, cudaEventDisableTiming);
        attr_done = true;
    }

    // 1: merged prep (default)
    k_prep<<<PREP_BLOCKS, 256>>>(xyz, features, Wq, Wk, Wv, Wp2, Wf1, Wf2, g1, b1, bq, bk, bv);
    cudaEventRecord(evPrep, 0);

    // side branch (s2): knn -> pos, then lnq (only needed by k_final)
    cudaStreamWaitEvent(s2, evPrep, 0);
    {
        dim3 kg(NPTS/16, BATCH);
        k_knn2<<<kg, 512, SMEM_KNN, s2>>>();
    }
    k_pgemm<<<NROWS/128, 256, SMEM_PG, s2>>>(Wp1, bp1, bp2);
    cudaEventRecord(evSide, s2);

    // main branch (default): qkv GEMM (kvmode split outputs)
    {
        dim3 g(ROWS/128, 12);
        k_mgemm<<<g, 256, MG_SMEM>>>(p_feat_h, p_feat_l, p_wqkvT_h, p_wqkvT_l,
                                     p_bqkv, nullptr, nullptr, nullptr, DIM, 768, 0, 1);
    }

    // lnq GEMM on side stream (overlaps with attn/fc)
    {
        dim3 g(ROWS/128, 4);
        k_mgemm<<<g, 256, MG_SMEM, s2>>>(p_lnf_h, p_lnf_l, p_wqkvT_h, p_wqkvT_l,
                                         bq, p_lnq, nullptr, nullptr, DIM, DOUT, 0, 0);
    }
    cudaEventRecord(evLnq, s2);

    // join (knn+pos ready), then attention
    cudaStreamWaitEvent(0, evSide, 0);
    k_attn<<<ROWS, 128>>>(attn_out);

    // fc1, fc2
    {
        dim3 g(ROWS/128, 4);
        k_mgemm<<<g, 256, MG_SMEM>>>(p_mid_h, p_mid_l, p_wf1T_h, p_wf1T_l,
                                     bf1, nullptr, p_fc1_h, p_fc1_l, DOUT, DOUT, 1, 0);
        k_mgemm<<<g, 256, MG_SMEM>>>(p_fc1_h, p_fc1_l, p_wf2T_h, p_wf2T_l,
                                     bf2, p_fc2, nullptr, nullptr, DOUT, DOUT, 0, 0);
    }

    // final LN + residual (needs lnq)
    cudaStreamWaitEvent(0, evLnq, 0);
    k_final<<<ROWS/8, 256>>>(g2, b2, out);
}